// round 1
// baseline (speedup 1.0000x reference)
#include <cuda_runtime.h>

#define Bc 2
#define Lc 2048
#define Hc 16
#define Ec 64
#define Dc 64
#define BHc (Bc*Hc)
#define BM 128
#define NCH 16
#define CHUNK 128

// Scratch (allocation-free rule: __device__ globals)
__device__ float g_csum[BHc * NCH * Dc];          // per-chunk V sums -> suffix offsets
__device__ float g_S[BHc * Lc * Dc];              // exclusive suffix sums of V over s>l

// ---------------- suffix-sum pipeline ----------------

__global__ void scan_chunks(const float* __restrict__ v) {
    int c = blockIdx.x, bh = blockIdx.y, d = threadIdx.x;
    int b = bh >> 4, h = bh & 15;
    float s = 0.f;
    #pragma unroll 8
    for (int r = 0; r < CHUNK; ++r) {
        int row = c * CHUNK + r;
        s += v[((b * Lc + row) * Hc + h) * Dc + d];
    }
    g_csum[(bh * NCH + c) * Dc + d] = s;
}

__global__ void scan_offsets() {
    int bh = blockIdx.x, d = threadIdx.x;
    float run = 0.f;
    for (int c = NCH - 1; c >= 0; --c) {
        float t = g_csum[(bh * NCH + c) * Dc + d];
        g_csum[(bh * NCH + c) * Dc + d] = run;   // exclusive suffix of chunk sums
        run += t;
    }
}

__global__ void scan_suffix(const float* __restrict__ v) {
    int c = blockIdx.x, bh = blockIdx.y, d = threadIdx.x;
    int b = bh >> 4, h = bh & 15;
    float run = g_csum[(bh * NCH + c) * Dc + d];
    #pragma unroll 4
    for (int r = CHUNK - 1; r >= 0; --r) {
        int row = c * CHUNK + r;
        g_S[(bh * Lc + row) * Dc + d] = run;     // exclusive: sum over s > row
        run += v[((b * Lc + row) * Hc + h) * Dc + d];
    }
}

// ---------------- causal flash attention (fp32 SIMT) ----------------
// 1 thread = 1 query row. q[64] and acc[64] register-resident.
// Lazy-rescale online softmax: rescale only when a new max appears (rare).

extern __shared__ float smem_attn[];

__global__ __launch_bounds__(128)
void attn_kernel(const float* __restrict__ Q,
                 const float* __restrict__ K,
                 const float* __restrict__ V,
                 float* __restrict__ O) {
    float* Ks = smem_attn;            // [128][64]
    float* Vs = smem_attn + BM * 64;  // [128][64]

    const int tid = threadIdx.x;
    const int bh  = blockIdx.y;
    const int b   = bh >> 4, h = bh & 15;
    // heavy tiles (large mtile) launch first for load balance
    const int mtile = (gridDim.x - 1) - blockIdx.x;
    const int l = mtile * BM + tid;

    // load + pre-scale q row into registers
    float q[64];
    {
        const float4* qr = (const float4*)&Q[((b * Lc + l) * Hc + h) * Ec];
        #pragma unroll
        for (int e4 = 0; e4 < 16; ++e4) {
            float4 t4 = qr[e4];
            q[4*e4+0] = t4.x * 0.125f;
            q[4*e4+1] = t4.y * 0.125f;
            q[4*e4+2] = t4.z * 0.125f;
            q[4*e4+3] = t4.w * 0.125f;
        }
    }

    float acc[64];
    #pragma unroll
    for (int d = 0; d < 64; ++d) acc[d] = 0.f;
    float M = 0.f;     // running max; 0 is always in the logit set (masked slots)
    float ssum = 0.f;  // sum of exp over unmasked slots only

    const int w = tid >> 5, lane = tid & 31;

    for (int t = 0; t <= mtile; ++t) {
        const int s0 = t * BM;
        __syncthreads();
        // cooperative coalesced tile load: warp w owns rows [32w, 32w+32)
        #pragma unroll 4
        for (int i = 0; i < 32; ++i) {
            int r = w * 32 + i;
            int s = s0 + r;
            int base = ((b * Lc + s) * Hc + h) * Ec + 2 * lane;
            float2 kk = *(const float2*)&K[base];
            float2 vv = *(const float2*)&V[base];
            *(float2*)&Ks[r * 64 + 2 * lane] = kk;
            *(float2*)&Vs[r * 64 + 2 * lane] = vv;
        }
        __syncthreads();

        const int jmax = (t == mtile) ? (tid + 1) : BM;
        #pragma unroll 2
        for (int j = 0; j < jmax; ++j) {
            // QK dot: 4 independent FMA chains for ILP
            const float* Kr = &Ks[j * 64];
            float a0 = 0.f, a1 = 0.f, a2 = 0.f, a3 = 0.f;
            #pragma unroll
            for (int e = 0; e < 64; e += 4) {
                float4 kk = *(const float4*)&Kr[e];
                a0 += q[e+0] * kk.x;
                a1 += q[e+1] * kk.y;
                a2 += q[e+2] * kk.z;
                a3 += q[e+3] * kk.w;
            }
            float sc = (a0 + a1) + (a2 + a3);

            if (sc > M) {   // rare: ~ln(L) times per row
                float alpha = __expf(M - sc);
                ssum *= alpha;
                #pragma unroll
                for (int d = 0; d < 64; ++d) acc[d] *= alpha;
                M = sc;
            }
            float p = __expf(sc - M);
            ssum += p;

            const float* Vr = &Vs[j * 64];
            #pragma unroll
            for (int d = 0; d < 64; d += 4) {
                float4 vv = *(const float4*)&Vr[d];
                acc[d+0] += p * vv.x;
                acc[d+1] += p * vv.y;
                acc[d+2] += p * vv.z;
                acc[d+3] += p * vv.w;
            }
        }
    }

    // epilogue: add masked-slot contributions exp(-M)*(suffix V) and denominator
    float em  = __expf(-M);
    float Z   = ssum + (float)(Lc - 1 - l) * em;
    float inv = 1.f / Z;

    const float4* Srow = (const float4*)&g_S[(bh * Lc + l) * Dc];
    float4* orow = (float4*)&O[((b * Lc + l) * Hc + h) * Dc];
    #pragma unroll
    for (int d4 = 0; d4 < 16; ++d4) {
        float4 s4 = Srow[d4];
        float4 o;
        o.x = (acc[4*d4+0] + em * s4.x) * inv;
        o.y = (acc[4*d4+1] + em * s4.y) * inv;
        o.z = (acc[4*d4+2] + em * s4.z) * inv;
        o.w = (acc[4*d4+3] + em * s4.w) * inv;
        orow[d4] = o;
    }
}

// ---------------- launch ----------------

extern "C" void kernel_launch(void* const* d_in, const int* in_sizes, int n_in,
                              void* d_out, int out_size) {
    const float* Q = (const float*)d_in[0];
    const float* K = (const float*)d_in[1];
    const float* V = (const float*)d_in[2];
    float* O = (float*)d_out;

    scan_chunks <<<dim3(NCH, BHc), 64>>>(V);
    scan_offsets<<<BHc, 64>>>();
    scan_suffix <<<dim3(NCH, BHc), 64>>>(V);

    const int smem = 2 * BM * 64 * (int)sizeof(float);  // 64 KB
    cudaFuncSetAttribute(attn_kernel, cudaFuncAttributeMaxDynamicSharedMemorySize, smem);
    attn_kernel<<<dim3(Lc / BM, BHc), 128, smem>>>(Q, K, V, O);
}

// round 3
// speedup vs baseline: 4.1269x; 4.1269x over previous
#include <cuda_runtime.h>
#include <cuda_bf16.h>
#include <cstdint>

#define Bc 2
#define Lc 2048
#define Hc 16
#define BHc 32
#define BM 128
#define NTILE 16
#define NCH 16
#define CHUNK 128

// ---------------- device scratch ----------------
__device__ float g_csum[BHc * NCH * 64];
__device__ float g_S[BHc * Lc * 64];                 // exclusive suffix sums of V over s>l
__device__ __nv_bfloat16 g_Khi[BHc * Lc * 64];
__device__ __nv_bfloat16 g_Klo[BHc * Lc * 64];
__device__ __nv_bfloat16 g_Vhi[BHc * Lc * 64];
__device__ __nv_bfloat16 g_Vlo[BHc * Lc * 64];

// ---------------- helpers ----------------
__device__ __forceinline__ uint32_t smem_u32(const void* p) {
    uint32_t a;
    asm("{ .reg .u64 t; cvta.to.shared.u64 t, %1; cvt.u32.u64 %0, t; }" : "=r"(a) : "l"(p));
    return a;
}
__device__ __forceinline__ float ex2f(float x) {
    float y; asm("ex2.approx.f32 %0, %1;" : "=f"(y) : "f"(x)); return y;
}
__device__ __forceinline__ void split2(float a, float b, uint32_t& hi, uint32_t& lo) {
    __nv_bfloat16 ha = __float2bfloat16(a), hb = __float2bfloat16(b);
    float ra = a - __bfloat162float(ha), rb = b - __bfloat162float(hb);
    __nv_bfloat162 H = __halves2bfloat162(ha, hb);
    __nv_bfloat162 L = __halves2bfloat162(__float2bfloat16(ra), __float2bfloat16(rb));
    hi = *reinterpret_cast<uint32_t*>(&H);
    lo = *reinterpret_cast<uint32_t*>(&L);
}
__device__ __forceinline__ void mma16816(float* c, const uint32_t* a, uint32_t b0, uint32_t b1) {
    asm volatile("mma.sync.aligned.m16n8k16.row.col.f32.bf16.bf16.f32 "
        "{%0,%1,%2,%3}, {%4,%5,%6,%7}, {%8,%9}, {%0,%1,%2,%3};"
        : "+f"(c[0]), "+f"(c[1]), "+f"(c[2]), "+f"(c[3])
        : "r"(a[0]), "r"(a[1]), "r"(a[2]), "r"(a[3]), "r"(b0), "r"(b1));
}
__device__ __forceinline__ void ldsm4(uint32_t addr, uint32_t* r) {
    asm volatile("ldmatrix.sync.aligned.m8n8.x4.shared.b16 {%0,%1,%2,%3}, [%4];"
        : "=r"(r[0]), "=r"(r[1]), "=r"(r[2]), "=r"(r[3]) : "r"(addr));
}
__device__ __forceinline__ void ldsm4t(uint32_t addr, uint32_t* r) {
    asm volatile("ldmatrix.sync.aligned.m8n8.x4.trans.shared.b16 {%0,%1,%2,%3}, [%4];"
        : "=r"(r[0]), "=r"(r[1]), "=r"(r[2]), "=r"(r[3]) : "r"(addr));
}
__device__ __forceinline__ void cpasync16(uint32_t dst, const void* src) {
    asm volatile("cp.async.cg.shared.global [%0], [%1], 16;" :: "r"(dst), "l"(src) : "memory");
}

// ---------------- suffix-sum pipeline (validated in R1) ----------------
__global__ void scan_chunks(const float* __restrict__ v) {
    int c = blockIdx.x, bh = blockIdx.y, d = threadIdx.x;
    int b = bh >> 4, h = bh & 15;
    float s = 0.f;
    #pragma unroll 8
    for (int r = 0; r < CHUNK; ++r)
        s += v[(((size_t)b * Lc + c * CHUNK + r) * Hc + h) * 64 + d];
    g_csum[(bh * NCH + c) * 64 + d] = s;
}
__global__ void scan_offsets() {
    int bh = blockIdx.x, d = threadIdx.x;
    float run = 0.f;
    for (int c = NCH - 1; c >= 0; --c) {
        float t = g_csum[(bh * NCH + c) * 64 + d];
        g_csum[(bh * NCH + c) * 64 + d] = run;
        run += t;
    }
}
__global__ void scan_suffix(const float* __restrict__ v) {
    int c = blockIdx.x, bh = blockIdx.y, d = threadIdx.x;
    int b = bh >> 4, h = bh & 15;
    float run = g_csum[(bh * NCH + c) * 64 + d];
    #pragma unroll 4
    for (int r = CHUNK - 1; r >= 0; --r) {
        int row = c * CHUNK + r;
        g_S[((size_t)bh * Lc + row) * 64 + d] = run;
        run += v[(((size_t)b * Lc + row) * Hc + h) * 64 + d];
    }
}

// ---------------- K/V pre-conversion: fp32 -> bf16 hi/lo, [bh][s][e] layout ----------------
__global__ void convert_kv(const float* __restrict__ K, const float* __restrict__ V) {
    size_t n = (size_t)blockIdx.x * 256 + threadIdx.x;
    int e = (int)(n & 63);
    int s = (int)((n >> 6) & 2047);
    int bh = (int)(n >> 17);
    int b = bh >> 4, h = bh & 15;
    size_t src = (((size_t)b * Lc + s) * Hc + h) * 64 + e;
    float k = K[src], v = V[src];
    __nv_bfloat16 kh = __float2bfloat16(k);
    g_Khi[n] = kh;
    g_Klo[n] = __float2bfloat16(k - __bfloat162float(kh));
    __nv_bfloat16 vh = __float2bfloat16(v);
    g_Vhi[n] = vh;
    g_Vlo[n] = __float2bfloat16(v - __bfloat162float(vh));
}

// ---------------- main attention kernel (warp MMA, double-buffered cp.async) ----------------
// smem stage layout: [Khi 16K][Klo 16K][Vhi 16K][Vlo 16K], 2 stages = 128KB
#define STAGE_BYTES 65536
#define QSCALE 0.18033688011112042f   // 0.125 * log2(e)

extern __shared__ char dynsm[];

__device__ __forceinline__ void issue_tile(uint32_t smbase, int stg, int bh, int t, int tid) {
    size_t rowbase = ((size_t)bh * Lc + (size_t)t * BM) << 6;   // *64 elements
    #pragma unroll
    for (int i = 0; i < 16; ++i) {
        const int arr = i >> 2;
        const int rem = (i & 3) * 256 + tid;
        const int s = rem >> 3, ch = rem & 7;
        const __nv_bfloat16* src;
        if (arr == 0)      src = g_Khi + rowbase + ((size_t)s << 6) + ch * 8;
        else if (arr == 1) src = g_Klo + rowbase + ((size_t)s << 6) + ch * 8;
        else if (arr == 2) src = g_Vhi + rowbase + ((size_t)s << 6) + ch * 8;
        else               src = g_Vlo + rowbase + ((size_t)s << 6) + ch * 8;
        uint32_t dst = smbase + stg * STAGE_BYTES + arr * 16384 + s * 128
                     + (((uint32_t)ch * 16) ^ (((uint32_t)s & 7) << 4));
        cpasync16(dst, src);
    }
    asm volatile("cp.async.commit_group;" ::: "memory");
}

__global__ void __launch_bounds__(256) attn_mma(const float* __restrict__ Q,
                                                float* __restrict__ O) {
    const uint32_t sm = smem_u32(dynsm);
    const int tid = threadIdx.x;
    const int w = tid >> 5, lane = tid & 31;
    const int g = lane >> 2, quad = lane & 3;
    const int bh = blockIdx.y, b = bh >> 4, h = bh & 15;
    const int mtile = (NTILE - 1) - (int)blockIdx.x;   // heavy tiles first

    // per-lane ldmatrix geometry (XOR-swizzled smem, 128B rows)
    const int ks_row = (lane & 7) + ((lane >> 4) << 3);      // K: s-row part
    const uint32_t k_col = ((uint32_t)((lane >> 3) & 1)) * 16;
    const int vs_row = (lane & 7) + (((lane >> 3) & 1) << 3); // V: s-row part
    const uint32_t v_col = ((uint32_t)(lane >> 4)) << 4;
    const uint32_t xo = ((uint32_t)(lane & 7)) << 4;

    // ---- load Q fragments (hi/lo split, scale folded in) ----
    uint32_t Qh[4][4], Ql[4][4];
    {
        const float* qb = Q + (((size_t)b * Lc + (size_t)mtile * BM + w * 16) * Hc + h) * 64;
        #pragma unroll
        for (int kc = 0; kc < 4; ++kc) {
            int e0 = kc * 16 + quad * 2;
            float2 v00 = *(const float2*)(qb + (size_t)g * 1024 + e0);
            float2 v10 = *(const float2*)(qb + (size_t)(g + 8) * 1024 + e0);
            float2 v01 = *(const float2*)(qb + (size_t)g * 1024 + e0 + 8);
            float2 v11 = *(const float2*)(qb + (size_t)(g + 8) * 1024 + e0 + 8);
            split2(v00.x * QSCALE, v00.y * QSCALE, Qh[kc][0], Ql[kc][0]);
            split2(v10.x * QSCALE, v10.y * QSCALE, Qh[kc][1], Ql[kc][1]);
            split2(v01.x * QSCALE, v01.y * QSCALE, Qh[kc][2], Ql[kc][2]);
            split2(v11.x * QSCALE, v11.y * QSCALE, Qh[kc][3], Ql[kc][3]);
        }
    }

    float Oa[8][4];
    #pragma unroll
    for (int i = 0; i < 8; ++i)
        #pragma unroll
        for (int j = 0; j < 4; ++j) Oa[i][j] = 0.f;
    float den0 = 0.f, den1 = 0.f;

    issue_tile(sm, 0, bh, 0, tid);

    #pragma unroll 1
    for (int t = 0; t <= mtile; ++t) {
        __syncthreads();   // previous iteration's reads of the other stage are done
        if (t < mtile) {
            issue_tile(sm, (t + 1) & 1, bh, t + 1, tid);
            asm volatile("cp.async.wait_group 1;" ::: "memory");
        } else {
            asm volatile("cp.async.wait_group 0;" ::: "memory");
        }
        __syncthreads();   // stage t data visible to all threads

        const uint32_t stg = sm + (uint32_t)(t & 1) * STAGE_BYTES;
        const uint32_t khi_b = stg, klo_b = stg + 16384;
        const uint32_t vhi_b = stg + 32768, vlo_b = stg + 49152;

        // ---- S = Q Kt (3-way bf16 split) ----
        float S[16][4];
        #pragma unroll
        for (int i = 0; i < 16; ++i)
            #pragma unroll
            for (int j = 0; j < 4; ++j) S[i][j] = 0.f;

        #pragma unroll
        for (int kc = 0; kc < 4; ++kc) {
            #pragma unroll
            for (int nbp = 0; nbp < 8; ++nbp) {
                uint32_t off = (uint32_t)(nbp * 16 + ks_row) * 128
                             + (((uint32_t)kc * 32 + k_col) ^ xo);
                uint32_t kb[4], kl4[4];
                ldsm4(khi_b + off, kb);
                ldsm4(klo_b + off, kl4);
                mma16816(S[2*nbp],   Qh[kc], kb[0], kb[1]);
                mma16816(S[2*nbp+1], Qh[kc], kb[2], kb[3]);
                mma16816(S[2*nbp],   Ql[kc], kb[0], kb[1]);
                mma16816(S[2*nbp+1], Ql[kc], kb[2], kb[3]);
                mma16816(S[2*nbp],   Qh[kc], kl4[0], kl4[1]);
                mma16816(S[2*nbp+1], Qh[kc], kl4[2], kl4[3]);
            }
        }

        // ---- exp + causal mask + pack P (C-frag layout == A-frag layout) ----
        const int lim0 = (t == mtile) ? (w * 16 + g) : 127;
        const int lim1 = (t == mtile) ? (w * 16 + g + 8) : 127;
        uint32_t Ph[8][4], Pl[8][4];
        #pragma unroll
        for (int nb = 0; nb < 16; ++nb) {
            int s0 = nb * 8 + quad * 2;
            float p0 = (s0     <= lim0) ? ex2f(S[nb][0]) : 0.f;
            float p1 = (s0 + 1 <= lim0) ? ex2f(S[nb][1]) : 0.f;
            float p2 = (s0     <= lim1) ? ex2f(S[nb][2]) : 0.f;
            float p3 = (s0 + 1 <= lim1) ? ex2f(S[nb][3]) : 0.f;
            den0 += p0 + p1;
            den1 += p2 + p3;
            split2(p0, p1, Ph[nb >> 1][(nb & 1) * 2],     Pl[nb >> 1][(nb & 1) * 2]);
            split2(p2, p3, Ph[nb >> 1][(nb & 1) * 2 + 1], Pl[nb >> 1][(nb & 1) * 2 + 1]);
        }

        // ---- O += P V (3-way bf16 split), V B-frags via ldmatrix.trans ----
        #pragma unroll
        for (int kcs = 0; kcs < 8; ++kcs) {
            #pragma unroll
            for (int nbp = 0; nbp < 4; ++nbp) {
                uint32_t off = (uint32_t)(kcs * 16 + vs_row) * 128
                             + (((uint32_t)nbp * 32 + v_col) ^ xo);
                uint32_t vb[4], vl4[4];
                ldsm4t(vhi_b + off, vb);
                ldsm4t(vlo_b + off, vl4);
                mma16816(Oa[2*nbp],   Ph[kcs], vb[0], vb[1]);
                mma16816(Oa[2*nbp+1], Ph[kcs], vb[2], vb[3]);
                mma16816(Oa[2*nbp],   Pl[kcs], vb[0], vb[1]);
                mma16816(Oa[2*nbp+1], Pl[kcs], vb[2], vb[3]);
                mma16816(Oa[2*nbp],   Ph[kcs], vl4[0], vl4[1]);
                mma16816(Oa[2*nbp+1], Ph[kcs], vl4[2], vl4[3]);
            }
        }
    }

    // ---- epilogue ----
    den0 += __shfl_xor_sync(0xffffffffu, den0, 1);
    den0 += __shfl_xor_sync(0xffffffffu, den0, 2);
    den1 += __shfl_xor_sync(0xffffffffu, den1, 1);
    den1 += __shfl_xor_sync(0xffffffffu, den1, 2);

    const int r0g = mtile * BM + w * 16 + g;
    const int r1g = r0g + 8;
    const float inv0 = 1.f / (den0 + (float)(Lc - 1 - r0g));
    const float inv1 = 1.f / (den1 + (float)(Lc - 1 - r1g));

    const size_t ob0 = (((size_t)b * Lc + r0g) * Hc + h) * 64;
    const size_t ob1 = (((size_t)b * Lc + r1g) * Hc + h) * 64;
    const size_t sb0 = ((size_t)bh * Lc + r0g) * 64;
    const size_t sb1 = ((size_t)bh * Lc + r1g) * 64;

    #pragma unroll
    for (int nb = 0; nb < 8; ++nb) {
        int d0 = nb * 8 + quad * 2;
        float2 s0 = *(const float2*)&g_S[sb0 + d0];
        float2 s1 = *(const float2*)&g_S[sb1 + d0];
        float2 o0 = make_float2((Oa[nb][0] + s0.x) * inv0, (Oa[nb][1] + s0.y) * inv0);
        float2 o1 = make_float2((Oa[nb][2] + s1.x) * inv1, (Oa[nb][3] + s1.y) * inv1);
        *(float2*)&O[ob0 + d0] = o0;
        *(float2*)&O[ob1 + d0] = o1;
    }
}

// ---------------- launch ----------------
extern "C" void kernel_launch(void* const* d_in, const int* in_sizes, int n_in,
                              void* d_out, int out_size) {
    const float* Q = (const float*)d_in[0];
    const float* K = (const float*)d_in[1];
    const float* V = (const float*)d_in[2];
    float* O = (float*)d_out;

    convert_kv<<<(BHc * Lc * 64) / 256, 256>>>(K, V);
    scan_chunks <<<dim3(NCH, BHc), 64>>>(V);
    scan_offsets<<<BHc, 64>>>();
    scan_suffix <<<dim3(NCH, BHc), 64>>>(V);

    cudaFuncSetAttribute(attn_mma, cudaFuncAttributeMaxDynamicSharedMemorySize, 2 * STAGE_BYTES);
    attn_mma<<<dim3(NTILE, BHc), 256, 2 * STAGE_BYTES>>>(Q, O);
}